// round 2
// baseline (speedup 1.0000x reference)
#include <cuda_runtime.h>
#include <math.h>

#define N_NODES 10000
#define N_EDGES 80000
#define E_TOT   90000      // edges + self loops
#define IN_DIM  768
#define HID     256
#define HEADS   8
#define F1      (HEADS*HID)   // 2048
#define NEG_SLOPE 0.2f

// ---------------- scratch (static device globals; no allocation) ----------------
__device__ float g_h1  [(size_t)N_NODES * F1];   // x @ W1
__device__ float g_agg1[(size_t)N_NODES * F1];   // layer-1 aggregation, then ELU in place
__device__ float g_h2  [(size_t)N_NODES * F1];   // elu @ W2
__device__ float g_agg2[(size_t)N_NODES * F1];   // layer-2 aggregation
__device__ float g_h2m [(size_t)N_NODES * HID];  // head-mean + b2
__device__ float g_as  [N_NODES * HEADS];
__device__ float g_ad  [N_NODES * HEADS];
__device__ float g_m   [N_NODES * HEADS];
__device__ float g_den [N_NODES * HEADS];
__device__ float g_p   [E_TOT * HEADS];
__device__ int   g_ei64;                         // 1 if edge_index stored as int64

// ---------------- edge-index dtype detection ------------------------------------
// Samples the first 64 elements interpreted as int64. Genuine int64 indices are
// all in [0, N_NODES). If the harness narrowed to int32, each int64-read packs
// two random indices -> values >= 2^32 almost surely -> classified int32.
// Only touches bytes [0, 512) — in bounds for both layouts.
__global__ void detect_kernel(const void* __restrict__ ei)
{
    const long long* p = (const long long*)ei;
    int ok = 1;
    for (int i = 0; i < 64; i++) {
        long long v = p[i];
        if (v < 0 || v >= N_NODES) { ok = 0; break; }
    }
    g_ei64 = ok;
}

__device__ __forceinline__ bool edge_sd(const void* __restrict__ ei,
                                        int e, int& s, int& d)
{
    if (e >= N_EDGES) { s = d = e - N_EDGES; return true; }   // self loop
    if (g_ei64) {
        const long long* p = (const long long*)ei;
        s = (int)p[e];
        d = (int)p[N_EDGES + e];
    } else {
        const int* p = (const int*)ei;
        s = p[e];
        d = p[N_EDGES + e];
    }
    return ((unsigned)s < N_NODES) && ((unsigned)d < N_NODES);
}

// ---------------- SGEMM: C[M,N] = A[M,K] @ B[K,N] (+ optional bias+relu) --------
// 128x128 block, 8x8 per thread, 256 threads, BK=8. N%128==0, K%8==0 assumed
// (true for all three GEMMs: N in {2048,2048,256}, K in {768,2048,256}).
template<int EPI>   // 0 = plain store, 1 = +bias then relu
__global__ __launch_bounds__(256)
void sgemm_kernel(const float* __restrict__ A, const float* __restrict__ B,
                  float* __restrict__ C, int M, int N, int K,
                  const float* __restrict__ bias)
{
    const int BM = 128, BN = 128, BK = 8;
    __shared__ float As[BK][BM];
    __shared__ float Bs[BK][BN];

    int tid = threadIdx.x;
    int tx = tid & 15;           // 0..15 -> 8 cols each
    int ty = tid >> 4;           // 0..15 -> 8 rows each
    int row0 = blockIdx.y * BM;
    int col0 = blockIdx.x * BN;

    // A tile load: 128 rows x 8 k, float4 per thread
    int a_row = tid >> 1;                 // 0..127
    int a_k   = (tid & 1) * 4;            // 0 or 4
    // B tile load: 8 k x 128 cols, float4 per thread
    int b_k   = tid >> 5;                 // 0..7
    int b_col = (tid & 31) * 4;           // 0..124

    float acc[8][8];
    #pragma unroll
    for (int i = 0; i < 8; i++)
        #pragma unroll
        for (int j = 0; j < 8; j++) acc[i][j] = 0.f;

    for (int k0 = 0; k0 < K; k0 += BK) {
        float4 av;
        int ar = row0 + a_row;
        if (ar < M) av = *(const float4*)(A + (size_t)ar * K + k0 + a_k);
        else        av = make_float4(0.f, 0.f, 0.f, 0.f);
        As[a_k + 0][a_row] = av.x;
        As[a_k + 1][a_row] = av.y;
        As[a_k + 2][a_row] = av.z;
        As[a_k + 3][a_row] = av.w;

        float4 bv = *(const float4*)(B + (size_t)(k0 + b_k) * N + col0 + b_col);
        *(float4*)&Bs[b_k][b_col] = bv;
        __syncthreads();

        #pragma unroll
        for (int kk = 0; kk < BK; kk++) {
            float af[8], bf[8];
            #pragma unroll
            for (int i = 0; i < 8; i += 4)
                *(float4*)&af[i] = *(const float4*)&As[kk][ty * 8 + i];
            #pragma unroll
            for (int j = 0; j < 8; j += 4)
                *(float4*)&bf[j] = *(const float4*)&Bs[kk][tx * 8 + j];
            #pragma unroll
            for (int i = 0; i < 8; i++)
                #pragma unroll
                for (int j = 0; j < 8; j++)
                    acc[i][j] = fmaf(af[i], bf[j], acc[i][j]);
        }
        __syncthreads();
    }

    #pragma unroll
    for (int i = 0; i < 8; i++) {
        int r = row0 + ty * 8 + i;
        if (r >= M) continue;
        #pragma unroll
        for (int j = 0; j < 8; j += 4) {
            int c = col0 + tx * 8 + j;
            float4 v = make_float4(acc[i][j], acc[i][j+1], acc[i][j+2], acc[i][j+3]);
            if (EPI == 1) {
                v.x = fmaxf(v.x + bias[c + 0], 0.f);
                v.y = fmaxf(v.y + bias[c + 1], 0.f);
                v.z = fmaxf(v.z + bias[c + 2], 0.f);
                v.w = fmaxf(v.w + bias[c + 3], 0.f);
            }
            *(float4*)(C + (size_t)r * N + c) = v;
        }
    }
}

// ---------------- per-(node,head) attention logits: one warp each --------------
__global__ __launch_bounds__(256)
void alpha_kernel(const float* __restrict__ h, const float* __restrict__ a_src,
                  const float* __restrict__ a_dst,
                  float* __restrict__ as_o, float* __restrict__ ad_o)
{
    int warp = (blockIdx.x * blockDim.x + threadIdx.x) >> 5;
    int lane = threadIdx.x & 31;
    if (warp >= N_NODES * HEADS) return;
    int n  = warp / HEADS;
    int hd = warp % HEADS;
    const float* hp  = h + (size_t)n * F1 + hd * HID;
    const float* asp = a_src + hd * HID;
    const float* adp = a_dst + hd * HID;
    float s = 0.f, d = 0.f;
    #pragma unroll
    for (int i = lane; i < HID; i += 32) {
        float v = hp[i];
        s = fmaf(v, asp[i], s);
        d = fmaf(v, adp[i], d);
    }
    #pragma unroll
    for (int o = 16; o; o >>= 1) {
        s += __shfl_down_sync(0xffffffffu, s, o);
        d += __shfl_down_sync(0xffffffffu, d, o);
    }
    if (lane == 0) { as_o[warp] = s; ad_o[warp] = d; }
}

// ---------------- init per-layer state: m=-inf, den=0, agg=0 -------------------
__global__ void init_kernel(float* __restrict__ m, float* __restrict__ den,
                            float* __restrict__ agg, int nAgg)
{
    int i = blockIdx.x * blockDim.x + threadIdx.x;
    if (i < N_NODES * HEADS) { m[i] = -INFINITY; den[i] = 0.f; }
    if (i < nAgg) agg[i] = 0.f;
}

__device__ __forceinline__ void atomicMaxFloat(float* addr, float val)
{
    // safe for finite values with -inf init
    if (val >= 0.f) atomicMax((int*)addr, __float_as_int(val));
    else            atomicMin((unsigned int*)addr, __float_as_uint(val));
}

__global__ void edge_max_kernel(const void* __restrict__ ei,
                                const float* __restrict__ as, const float* __restrict__ ad,
                                float* __restrict__ m)
{
    int e = blockIdx.x * blockDim.x + threadIdx.x;
    if (e >= E_TOT) return;
    int s, d;
    if (!edge_sd(ei, e, s, d)) return;
    #pragma unroll
    for (int h = 0; h < HEADS; h++) {
        float v = as[s * HEADS + h] + ad[d * HEADS + h];
        v = v >= 0.f ? v : NEG_SLOPE * v;
        atomicMaxFloat(&m[d * HEADS + h], v);
    }
}

__global__ void edge_exp_kernel(const void* __restrict__ ei,
                                const float* __restrict__ as, const float* __restrict__ ad,
                                const float* __restrict__ m,
                                float* __restrict__ p, float* __restrict__ den)
{
    int e = blockIdx.x * blockDim.x + threadIdx.x;
    if (e >= E_TOT) return;
    int s, d;
    if (!edge_sd(ei, e, s, d)) return;
    #pragma unroll
    for (int h = 0; h < HEADS; h++) {
        float v = as[s * HEADS + h] + ad[d * HEADS + h];
        v = v >= 0.f ? v : NEG_SLOPE * v;
        float pe = expf(v - m[d * HEADS + h]);
        p[e * HEADS + h] = pe;
        atomicAdd(&den[d * HEADS + h], pe);
    }
}

// one thread per (edge, 4 channels): float4 gather + 4 scatter atomics
__global__ __launch_bounds__(256)
void edge_agg_kernel(const void* __restrict__ ei,
                     const float* __restrict__ h, const float* __restrict__ p,
                     const float* __restrict__ den, float* __restrict__ agg)
{
    int tid = blockIdx.x * blockDim.x + threadIdx.x;
    const int QPE = F1 / 4;                 // 512 quads per edge
    if (tid >= E_TOT * QPE) return;
    int e = tid / QPE;
    int q = (tid - e * QPE) * 4;            // channel base, multiple of 4
    int hd = q >> 8;                        // head index (256 ch per head)
    int s, d;
    if (!edge_sd(ei, e, s, d)) return;
    float alpha = p[e * HEADS + hd] / (den[d * HEADS + hd] + 1e-16f);
    float4 hv = *(const float4*)(h + (size_t)s * F1 + q);
    float* ap = agg + (size_t)d * F1 + q;
    atomicAdd(ap + 0, alpha * hv.x);
    atomicAdd(ap + 1, alpha * hv.y);
    atomicAdd(ap + 2, alpha * hv.z);
    atomicAdd(ap + 3, alpha * hv.w);
}

// ---------------- bias + ELU in place -------------------------------------------
__global__ void bias_elu_kernel(float* __restrict__ agg, const float* __restrict__ b)
{
    int i = blockIdx.x * blockDim.x + threadIdx.x;
    if (i >= N_NODES * F1) return;
    float v = agg[i] + b[i % F1];
    agg[i] = v > 0.f ? v : (expf(v) - 1.f);
}

// ---------------- mean over heads + b2 -------------------------------------------
__global__ void mean_kernel(const float* __restrict__ agg, const float* __restrict__ b2,
                            float* __restrict__ out)
{
    int i = blockIdx.x * blockDim.x + threadIdx.x;
    if (i >= N_NODES * HID) return;
    int n = i / HID;
    int c = i - n * HID;
    float s = 0.f;
    #pragma unroll
    for (int h = 0; h < HEADS; h++) s += agg[(size_t)n * F1 + h * HID + c];
    out[i] = s * (1.f / HEADS) + b2[c];
}

// ---------------- launch ---------------------------------------------------------
extern "C" void kernel_launch(void* const* d_in, const int* in_sizes, int n_in,
                              void* d_out, int out_size)
{
    const float* x      = (const float*)d_in[0];
    const void*  eindex = d_in[1];                  // int32 or int64, detected on device
    const float* W1     = (const float*)d_in[2];
    const float* a_src1 = (const float*)d_in[3];
    const float* a_dst1 = (const float*)d_in[4];
    const float* b1     = (const float*)d_in[5];
    const float* W2     = (const float*)d_in[6];
    const float* a_src2 = (const float*)d_in[7];
    const float* a_dst2 = (const float*)d_in[8];
    const float* b2     = (const float*)d_in[9];
    const float* Wp     = (const float*)d_in[10];
    const float* bp     = (const float*)d_in[11];
    float*       out    = (float*)d_out;

    float *h1, *agg1, *h2, *agg2, *h2m, *as, *ad, *m, *den, *p;
    cudaGetSymbolAddress((void**)&h1,   g_h1);
    cudaGetSymbolAddress((void**)&agg1, g_agg1);
    cudaGetSymbolAddress((void**)&h2,   g_h2);
    cudaGetSymbolAddress((void**)&agg2, g_agg2);
    cudaGetSymbolAddress((void**)&h2m,  g_h2m);
    cudaGetSymbolAddress((void**)&as,   g_as);
    cudaGetSymbolAddress((void**)&ad,   g_ad);
    cudaGetSymbolAddress((void**)&m,    g_m);
    cudaGetSymbolAddress((void**)&den,  g_den);
    cudaGetSymbolAddress((void**)&p,    g_p);

    const int nAgg = N_NODES * F1;                 // 20,480,000
    const int TB = 256;
    dim3 gemm_blk(256);

    detect_kernel<<<1, 1>>>(eindex);

    // ---- layer 1 ----
    {
        dim3 grid(F1 / 128, (N_NODES + 127) / 128);
        sgemm_kernel<0><<<grid, gemm_blk>>>(x, W1, h1, N_NODES, F1, IN_DIM, nullptr);
    }
    alpha_kernel<<<(N_NODES * HEADS * 32 + TB - 1) / TB, TB>>>(h1, a_src1, a_dst1, as, ad);
    init_kernel<<<(nAgg + TB - 1) / TB, TB>>>(m, den, agg1, nAgg);
    edge_max_kernel<<<(E_TOT + TB - 1) / TB, TB>>>(eindex, as, ad, m);
    edge_exp_kernel<<<(E_TOT + TB - 1) / TB, TB>>>(eindex, as, ad, m, p, den);
    edge_agg_kernel<<<(E_TOT * (F1 / 4) + TB - 1) / TB, TB>>>(eindex, h1, p, den, agg1);
    bias_elu_kernel<<<(nAgg + TB - 1) / TB, TB>>>(agg1, b1);

    // ---- layer 2 ----
    {
        dim3 grid(F1 / 128, (N_NODES + 127) / 128);
        sgemm_kernel<0><<<grid, gemm_blk>>>(agg1, W2, h2, N_NODES, F1, F1, nullptr);
    }
    alpha_kernel<<<(N_NODES * HEADS * 32 + TB - 1) / TB, TB>>>(h2, a_src2, a_dst2, as, ad);
    init_kernel<<<(nAgg + TB - 1) / TB, TB>>>(m, den, agg2, nAgg);
    edge_max_kernel<<<(E_TOT + TB - 1) / TB, TB>>>(eindex, as, ad, m);
    edge_exp_kernel<<<(E_TOT + TB - 1) / TB, TB>>>(eindex, as, ad, m, p, den);
    edge_agg_kernel<<<(E_TOT * (F1 / 4) + TB - 1) / TB, TB>>>(eindex, h2, p, den, agg2);
    mean_kernel<<<(N_NODES * HID + TB - 1) / TB, TB>>>(agg2, b2, h2m);

    // ---- projection + relu ----
    {
        dim3 grid(HID / 128, (N_NODES + 127) / 128);
        sgemm_kernel<1><<<grid, gemm_blk>>>(h2m, Wp, out, N_NODES, HID, HID, bp);
    }
}

// round 5
// speedup vs baseline: 1.8992x; 1.8992x over previous
#include <cuda_runtime.h>
#include <math.h>
#include <stdint.h>

#define N_NODES 10000
#define N_EDGES 80000
#define E_TOT   90000      // edges + self loops
#define IN_DIM  768
#define HID     256
#define HEADS   8
#define F1      (HEADS*HID)   // 2048
#define NEG_SLOPE 0.2f

// ---------------- scratch (static device globals; no allocation) ----------------
__device__ float g_h1  [(size_t)N_NODES * F1];   // x @ W1
__device__ float g_agg1[(size_t)N_NODES * F1];   // layer-1 aggregation, then ELU in place
__device__ float g_h2  [(size_t)N_NODES * F1];   // elu @ W2
__device__ float g_agg2[(size_t)N_NODES * F1];   // layer-2 aggregation
__device__ float g_h2m [(size_t)N_NODES * HID];  // head-mean + b2
__device__ float g_as  [N_NODES * HEADS];
__device__ float g_ad  [N_NODES * HEADS];
__device__ float g_m   [N_NODES * HEADS];
__device__ float g_den [N_NODES * HEADS];
__device__ float g_p   [E_TOT * HEADS];
__device__ int   g_ei64;                         // 1 if edge_index stored as int64
__device__ float g_wt1 [(size_t)F1 * IN_DIM];    // W1^T  [2048][768]
__device__ float g_wt2 [(size_t)F1 * F1];        // W2^T  [2048][2048]
__device__ float g_wtp [(size_t)HID * HID];      // Wp^T  [256][256]

// ======================  tf32 mma.sync GEMM  ====================================
// C[M,N] = A[M,K] @ Bt[N,K]^T.  CTA tile 128x128, 8 warps (2x4), warp tile 64x32,
// m16n8k8 tf32 frags, BK=16 double-buffered. Requires N%128==0, K%16==0.

__device__ __forceinline__ uint32_t f2tf32(float f) {
    uint32_t u;
    asm("cvt.rna.tf32.f32 %0, %1;" : "=r"(u) : "f"(f));
    return u;
}

__device__ __forceinline__ void mma_tf32(float* c, const uint32_t* a, const uint32_t* b) {
    asm volatile(
        "mma.sync.aligned.m16n8k8.row.col.f32.tf32.tf32.f32 "
        "{%0,%1,%2,%3}, {%4,%5,%6,%7}, {%8,%9}, {%0,%1,%2,%3};"
        : "+f"(c[0]), "+f"(c[1]), "+f"(c[2]), "+f"(c[3])
        : "r"(a[0]), "r"(a[1]), "r"(a[2]), "r"(a[3]), "r"(b[0]), "r"(b[1]));
}

#define BKK  16
#define KPAD 20    // 16 + 4 pad -> conflict-free fragment loads

template<int EPI>   // 0 = plain store, 1 = +bias then relu
__global__ __launch_bounds__(256, 2)
void mma_gemm_kernel(const float* __restrict__ A, const float* __restrict__ Bt,
                     float* __restrict__ C, int M, int N, int K,
                     const float* __restrict__ bias)
{
    __shared__ __align__(16) uint32_t As[2][128 * KPAD];
    __shared__ __align__(16) uint32_t Bs[2][128 * KPAD];

    const int tid  = threadIdx.x;
    const int lane = tid & 31;
    const int wid  = tid >> 5;
    const int gid  = lane >> 2;     // 0..7
    const int tig  = lane & 3;      // 0..3
    const int wm   = (wid & 1) * 64;
    const int wn   = (wid >> 1) * 32;
    const int row0 = blockIdx.y * 128;
    const int col0 = blockIdx.x * 128;

    float acc[4][4][4];
    #pragma unroll
    for (int mt = 0; mt < 4; mt++)
        #pragma unroll
        for (int nt = 0; nt < 4; nt++)
            #pragma unroll
            for (int i = 0; i < 4; i++) acc[mt][nt][i] = 0.f;

    const int S = K / BKK;

    // ---- stage loader: global -> tf32-converted smem [row][k] ----
    auto load_stage = [&](int s, int buf) {
        int k0 = s * BKK;
        #pragma unroll
        for (int t = 0; t < 2; t++) {
            int idx = tid + t * 256;        // 0..511
            int row = idx >> 2;             // 0..127
            int kq  = (idx & 3) * 4;        // 0,4,8,12
            float4 v = make_float4(0.f, 0.f, 0.f, 0.f);
            if (row0 + row < M)
                v = *(const float4*)(A + (size_t)(row0 + row) * K + k0 + kq);
            uint4 u = make_uint4(f2tf32(v.x), f2tf32(v.y), f2tf32(v.z), f2tf32(v.w));
            *(uint4*)&As[buf][row * KPAD + kq] = u;
            float4 w = *(const float4*)(Bt + (size_t)(col0 + row) * K + k0 + kq);
            uint4 uw = make_uint4(f2tf32(w.x), f2tf32(w.y), f2tf32(w.z), f2tf32(w.w));
            *(uint4*)&Bs[buf][row * KPAD + kq] = uw;
        }
    };

    load_stage(0, 0);
    __syncthreads();

    for (int s = 0; s < S; s++) {
        int buf = s & 1;
        if (s + 1 < S) load_stage(s + 1, buf ^ 1);

        #pragma unroll
        for (int kk = 0; kk < 2; kk++) {
            uint32_t a[4][4], b[4][2];
            #pragma unroll
            for (int mt = 0; mt < 4; mt++) {
                int m = wm + mt * 16;
                int kb = kk * 8;
                a[mt][0] = As[buf][(m + gid)     * KPAD + kb + tig];
                a[mt][1] = As[buf][(m + gid + 8) * KPAD + kb + tig];
                a[mt][2] = As[buf][(m + gid)     * KPAD + kb + tig + 4];
                a[mt][3] = As[buf][(m + gid + 8) * KPAD + kb + tig + 4];
            }
            #pragma unroll
            for (int nt = 0; nt < 4; nt++) {
                int n = wn + nt * 8;
                int kb = kk * 8;
                b[nt][0] = Bs[buf][(n + gid) * KPAD + kb + tig];
                b[nt][1] = Bs[buf][(n + gid) * KPAD + kb + tig + 4];
            }
            #pragma unroll
            for (int mt = 0; mt < 4; mt++)
                #pragma unroll
                for (int nt = 0; nt < 4; nt++)
                    mma_tf32(acc[mt][nt], a[mt], b[nt]);
        }
        __syncthreads();
    }

    // ---- epilogue: float2 stores, guarded on M ----
    #pragma unroll
    for (int mt = 0; mt < 4; mt++) {
        int r0 = row0 + wm + mt * 16 + gid;
        int r1 = r0 + 8;
        #pragma unroll
        for (int nt = 0; nt < 4; nt++) {
            int c = col0 + wn + nt * 8 + tig * 2;
            float2 v0 = make_float2(acc[mt][nt][0], acc[mt][nt][1]);
            float2 v1 = make_float2(acc[mt][nt][2], acc[mt][nt][3]);
            if (EPI) {
                float bc0 = bias[c], bc1 = bias[c + 1];
                v0.x = fmaxf(v0.x + bc0, 0.f); v0.y = fmaxf(v0.y + bc1, 0.f);
                v1.x = fmaxf(v1.x + bc0, 0.f); v1.y = fmaxf(v1.y + bc1, 0.f);
            }
            if (r0 < M) *(float2*)(C + (size_t)r0 * N + c) = v0;
            if (r1 < M) *(float2*)(C + (size_t)r1 * N + c) = v1;
        }
    }
}

// ---------------- W[K][N] -> Wt[N][K] transpose ---------------------------------
__global__ __launch_bounds__(256)
void transpose_kernel(const float* __restrict__ W, float* __restrict__ Wt,
                      int K, int N)
{
    __shared__ float t[32][33];
    int n0 = blockIdx.x * 32, k0 = blockIdx.y * 32;
    int x = threadIdx.x, y0 = threadIdx.y;     // blockDim (32, 8)
    #pragma unroll
    for (int dy = 0; dy < 32; dy += 8) {
        int k = k0 + y0 + dy, n = n0 + x;
        t[y0 + dy][x] = (k < K && n < N) ? W[(size_t)k * N + n] : 0.f;
    }
    __syncthreads();
    #pragma unroll
    for (int dy = 0; dy < 32; dy += 8) {
        int n = n0 + y0 + dy, k = k0 + x;
        if (n < N && k < K) Wt[(size_t)n * K + k] = t[x][y0 + dy];
    }
}

// ---------------- edge-index dtype detection ------------------------------------
__global__ void detect_kernel(const void* __restrict__ ei)
{
    const long long* p = (const long long*)ei;
    int ok = 1;
    for (int i = 0; i < 64; i++) {
        long long v = p[i];
        if (v < 0 || v >= N_NODES) { ok = 0; break; }
    }
    g_ei64 = ok;
}

__device__ __forceinline__ bool edge_sd(const void* __restrict__ ei,
                                        int e, int& s, int& d)
{
    if (e >= N_EDGES) { s = d = e - N_EDGES; return true; }   // self loop
    if (g_ei64) {
        const long long* p = (const long long*)ei;
        s = (int)p[e];
        d = (int)p[N_EDGES + e];
    } else {
        const int* p = (const int*)ei;
        s = p[e];
        d = p[N_EDGES + e];
    }
    return ((unsigned)s < N_NODES) && ((unsigned)d < N_NODES);
}

// ---------------- per-(node,head) attention logits: one warp each --------------
__global__ __launch_bounds__(256)
void alpha_kernel(const float* __restrict__ h, const float* __restrict__ a_src,
                  const float* __restrict__ a_dst,
                  float* __restrict__ as_o, float* __restrict__ ad_o)
{
    int warp = (blockIdx.x * blockDim.x + threadIdx.x) >> 5;
    int lane = threadIdx.x & 31;
    if (warp >= N_NODES * HEADS) return;
    int n  = warp / HEADS;
    int hd = warp % HEADS;
    const float* hp  = h + (size_t)n * F1 + hd * HID;
    const float* asp = a_src + hd * HID;
    const float* adp = a_dst + hd * HID;
    float s = 0.f, d = 0.f;
    #pragma unroll
    for (int i = lane; i < HID; i += 32) {
        float v = hp[i];
        s = fmaf(v, asp[i], s);
        d = fmaf(v, adp[i], d);
    }
    #pragma unroll
    for (int o = 16; o; o >>= 1) {
        s += __shfl_down_sync(0xffffffffu, s, o);
        d += __shfl_down_sync(0xffffffffu, d, o);
    }
    if (lane == 0) { as_o[warp] = s; ad_o[warp] = d; }
}

// ---------------- init per-layer state: m=-inf, den=0, agg=0 -------------------
__global__ void init_kernel(float* __restrict__ m, float* __restrict__ den,
                            float4* __restrict__ agg, int nAgg4)
{
    int i = blockIdx.x * blockDim.x + threadIdx.x;
    if (i < N_NODES * HEADS) { m[i] = -INFINITY; den[i] = 0.f; }
    if (i < nAgg4) agg[i] = make_float4(0.f, 0.f, 0.f, 0.f);
}

__device__ __forceinline__ void atomicMaxFloat(float* addr, float val)
{
    if (val >= 0.f) atomicMax((int*)addr, __float_as_int(val));
    else            atomicMin((unsigned int*)addr, __float_as_uint(val));
}

__global__ void edge_max_kernel(const void* __restrict__ ei,
                                const float* __restrict__ as, const float* __restrict__ ad,
                                float* __restrict__ m)
{
    int e = blockIdx.x * blockDim.x + threadIdx.x;
    if (e >= E_TOT) return;
    int s, d;
    if (!edge_sd(ei, e, s, d)) return;
    #pragma unroll
    for (int h = 0; h < HEADS; h++) {
        float v = as[s * HEADS + h] + ad[d * HEADS + h];
        v = v >= 0.f ? v : NEG_SLOPE * v;
        atomicMaxFloat(&m[d * HEADS + h], v);
    }
}

__global__ void edge_exp_kernel(const void* __restrict__ ei,
                                const float* __restrict__ as, const float* __restrict__ ad,
                                const float* __restrict__ m,
                                float* __restrict__ p, float* __restrict__ den)
{
    int e = blockIdx.x * blockDim.x + threadIdx.x;
    if (e >= E_TOT) return;
    int s, d;
    if (!edge_sd(ei, e, s, d)) return;
    #pragma unroll
    for (int h = 0; h < HEADS; h++) {
        float v = as[s * HEADS + h] + ad[d * HEADS + h];
        v = v >= 0.f ? v : NEG_SLOPE * v;
        float pe = expf(v - m[d * HEADS + h]);
        p[e * HEADS + h] = pe;
        atomicAdd(&den[d * HEADS + h], pe);
    }
}

// one thread per (edge, 4 channels): float4 gather + 4 scatter atomics
__global__ __launch_bounds__(256)
void edge_agg_kernel(const void* __restrict__ ei,
                     const float* __restrict__ h, const float* __restrict__ p,
                     const float* __restrict__ den, float* __restrict__ agg)
{
    int tid = blockIdx.x * blockDim.x + threadIdx.x;
    const int QPE = F1 / 4;                 // 512 quads per edge
    if (tid >= E_TOT * QPE) return;
    int e = tid / QPE;
    int q = (tid - e * QPE) * 4;            // channel base, multiple of 4
    int hd = q >> 8;                        // head index (256 ch per head)
    int s, d;
    if (!edge_sd(ei, e, s, d)) return;
    float alpha = p[e * HEADS + hd] / (den[d * HEADS + hd] + 1e-16f);
    float4 hv = *(const float4*)(h + (size_t)s * F1 + q);
    float* ap = agg + (size_t)d * F1 + q;
    atomicAdd(ap + 0, alpha * hv.x);
    atomicAdd(ap + 1, alpha * hv.y);
    atomicAdd(ap + 2, alpha * hv.z);
    atomicAdd(ap + 3, alpha * hv.w);
}

// ---------------- bias + ELU in place -------------------------------------------
__global__ void bias_elu_kernel(float* __restrict__ agg, const float* __restrict__ b)
{
    int i = blockIdx.x * blockDim.x + threadIdx.x;
    if (i >= N_NODES * F1) return;
    float v = agg[i] + b[i % F1];
    agg[i] = v > 0.f ? v : (expf(v) - 1.f);
}

// ---------------- mean over heads + b2 -------------------------------------------
__global__ void mean_kernel(const float* __restrict__ agg, const float* __restrict__ b2,
                            float* __restrict__ out)
{
    int i = blockIdx.x * blockDim.x + threadIdx.x;
    if (i >= N_NODES * HID) return;
    int n = i / HID;
    int c = i - n * HID;
    float s = 0.f;
    #pragma unroll
    for (int h = 0; h < HEADS; h++) s += agg[(size_t)n * F1 + h * HID + c];
    out[i] = s * (1.f / HEADS) + b2[c];
}

// ---------------- launch ---------------------------------------------------------
extern "C" void kernel_launch(void* const* d_in, const int* in_sizes, int n_in,
                              void* d_out, int out_size)
{
    const float* x      = (const float*)d_in[0];
    const void*  eindex = d_in[1];                  // int32 or int64, detected on device
    const float* W1     = (const float*)d_in[2];
    const float* a_src1 = (const float*)d_in[3];
    const float* a_dst1 = (const float*)d_in[4];
    const float* b1     = (const float*)d_in[5];
    const float* W2     = (const float*)d_in[6];
    const float* a_src2 = (const float*)d_in[7];
    const float* a_dst2 = (const float*)d_in[8];
    const float* b2     = (const float*)d_in[9];
    const float* Wp     = (const float*)d_in[10];
    const float* bp     = (const float*)d_in[11];
    float*       out    = (float*)d_out;

    float *h1, *agg1, *h2, *agg2, *h2m, *as, *ad, *m, *den, *p;
    float *wt1, *wt2, *wtp;
    cudaGetSymbolAddress((void**)&h1,   g_h1);
    cudaGetSymbolAddress((void**)&agg1, g_agg1);
    cudaGetSymbolAddress((void**)&h2,   g_h2);
    cudaGetSymbolAddress((void**)&agg2, g_agg2);
    cudaGetSymbolAddress((void**)&h2m,  g_h2m);
    cudaGetSymbolAddress((void**)&as,   g_as);
    cudaGetSymbolAddress((void**)&ad,   g_ad);
    cudaGetSymbolAddress((void**)&m,    g_m);
    cudaGetSymbolAddress((void**)&den,  g_den);
    cudaGetSymbolAddress((void**)&p,    g_p);
    cudaGetSymbolAddress((void**)&wt1,  g_wt1);
    cudaGetSymbolAddress((void**)&wt2,  g_wt2);
    cudaGetSymbolAddress((void**)&wtp,  g_wtp);

    const int nAgg  = N_NODES * F1;                 // 20,480,000
    const int nAgg4 = nAgg / 4;
    const int TB = 256;
    dim3 tblk(32, 8);
    const int MROWS = (N_NODES + 127) / 128;        // 79

    detect_kernel<<<1, 1>>>(eindex);
    transpose_kernel<<<dim3(F1 / 32, IN_DIM / 32), tblk>>>(W1, wt1, IN_DIM, F1);
    transpose_kernel<<<dim3(F1 / 32, F1 / 32),     tblk>>>(W2, wt2, F1, F1);
    transpose_kernel<<<dim3(HID / 32, HID / 32),   tblk>>>(Wp, wtp, HID, HID);

    // ---- layer 1 ----
    mma_gemm_kernel<0><<<dim3(F1 / 128, MROWS), 256>>>(x, wt1, h1,
                                                       N_NODES, F1, IN_DIM, nullptr);
    alpha_kernel<<<(N_NODES * HEADS * 32 + TB - 1) / TB, TB>>>(h1, a_src1, a_dst1, as, ad);
    init_kernel<<<(nAgg4 + TB - 1) / TB, TB>>>(m, den, (float4*)agg1, nAgg4);
    edge_max_kernel<<<(E_TOT + TB - 1) / TB, TB>>>(eindex, as, ad, m);
    edge_exp_kernel<<<(E_TOT + TB - 1) / TB, TB>>>(eindex, as, ad, m, p, den);
    edge_agg_kernel<<<(E_TOT * (F1 / 4) + TB - 1) / TB, TB>>>(eindex, h1, p, den, agg1);
    bias_elu_kernel<<<(nAgg + TB - 1) / TB, TB>>>(agg1, b1);

    // ---- layer 2 ----
    mma_gemm_kernel<0><<<dim3(F1 / 128, MROWS), 256>>>(agg1, wt2, h2,
                                                       N_NODES, F1, F1, nullptr);
    alpha_kernel<<<(N_NODES * HEADS * 32 + TB - 1) / TB, TB>>>(h2, a_src2, a_dst2, as, ad);
    init_kernel<<<(nAgg4 + TB - 1) / TB, TB>>>(m, den, (float4*)agg2, nAgg4);
    edge_max_kernel<<<(E_TOT + TB - 1) / TB, TB>>>(eindex, as, ad, m);
    edge_exp_kernel<<<(E_TOT + TB - 1) / TB, TB>>>(eindex, as, ad, m, p, den);
    edge_agg_kernel<<<(E_TOT * (F1 / 4) + TB - 1) / TB, TB>>>(eindex, h2, p, den, agg2);
    mean_kernel<<<(N_NODES * HID + TB - 1) / TB, TB>>>(agg2, b2, h2m);

    // ---- projection + relu ----
    mma_gemm_kernel<1><<<dim3(HID / 128, MROWS), 256>>>(h2m, wtp, out,
                                                        N_NODES, HID, HID, bp);
}

// round 7
// speedup vs baseline: 3.1234x; 1.6446x over previous
#include <cuda_runtime.h>
#include <math.h>
#include <stdint.h>

#define N_NODES 10000
#define N_EDGES 80000
#define E_TOT   90000      // edges + self loops
#define IN_DIM  768
#define HID     256
#define HEADS   8
#define F1      (HEADS*HID)   // 2048
#define NEG_SLOPE 0.2f

// ---------------- scratch (static device globals; no allocation) ----------------
__device__ float g_h1  [(size_t)N_NODES * F1];   // x @ W1
__device__ float g_agg1[(size_t)N_NODES * F1];   // layer-1 aggregated + bias + ELU
__device__ float g_h2  [(size_t)N_NODES * F1];   // agg1 @ W2
__device__ float g_h2m [(size_t)N_NODES * HID];  // layer-2 aggregated head-mean + b2
__device__ float g_as  [N_NODES * HEADS];
__device__ float g_ad  [N_NODES * HEADS];
__device__ float g_m   [N_NODES * HEADS];
__device__ float g_den [N_NODES * HEADS];
__device__ int   g_ei64;                         // 1 if edge_index stored as int64
__device__ float g_wt1 [(size_t)F1 * IN_DIM];    // W1^T  [2048][768]
__device__ float g_wt2 [(size_t)F1 * F1];        // W2^T  [2048][2048]
__device__ float g_wtp [(size_t)HID * HID];      // Wp^T  [256][256]
// CSR by dst
__device__ int   g_deg   [N_NODES];
__device__ int   g_rowptr[N_NODES + 1];
__device__ int   g_cursor[N_NODES];
__device__ int   g_col   [E_TOT];                // src node per CSR slot

// ======================  tf32 mma.sync GEMM  ====================================
__device__ __forceinline__ uint32_t f2tf32(float f) {
    uint32_t u;
    asm("cvt.rna.tf32.f32 %0, %1;" : "=r"(u) : "f"(f));
    return u;
}

__device__ __forceinline__ void mma_tf32(float* c, const uint32_t* a, const uint32_t* b) {
    asm volatile(
        "mma.sync.aligned.m16n8k8.row.col.f32.tf32.tf32.f32 "
        "{%0,%1,%2,%3}, {%4,%5,%6,%7}, {%8,%9}, {%0,%1,%2,%3};"
        : "+f"(c[0]), "+f"(c[1]), "+f"(c[2]), "+f"(c[3])
        : "r"(a[0]), "r"(a[1]), "r"(a[2]), "r"(a[3]), "r"(b[0]), "r"(b[1]));
}

#define BKK  16
#define KPAD 20    // 16 + 4 pad -> conflict-free fragment loads

template<int EPI>   // 0 = plain store, 1 = +bias then relu
__global__ __launch_bounds__(256, 2)
void mma_gemm_kernel(const float* __restrict__ A, const float* __restrict__ Bt,
                     float* __restrict__ C, int M, int N, int K,
                     const float* __restrict__ bias)
{
    __shared__ __align__(16) uint32_t As[2][128 * KPAD];
    __shared__ __align__(16) uint32_t Bs[2][128 * KPAD];

    const int tid  = threadIdx.x;
    const int lane = tid & 31;
    const int wid  = tid >> 5;
    const int gid  = lane >> 2;
    const int tig  = lane & 3;
    const int wm   = (wid & 1) * 64;
    const int wn   = (wid >> 1) * 32;
    const int row0 = blockIdx.y * 128;
    const int col0 = blockIdx.x * 128;

    float acc[4][4][4];
    #pragma unroll
    for (int mt = 0; mt < 4; mt++)
        #pragma unroll
        for (int nt = 0; nt < 4; nt++)
            #pragma unroll
            for (int i = 0; i < 4; i++) acc[mt][nt][i] = 0.f;

    const int S = K / BKK;

    auto load_stage = [&](int s, int buf) {
        int k0 = s * BKK;
        #pragma unroll
        for (int t = 0; t < 2; t++) {
            int idx = tid + t * 256;
            int row = idx >> 2;
            int kq  = (idx & 3) * 4;
            float4 v = make_float4(0.f, 0.f, 0.f, 0.f);
            if (row0 + row < M)
                v = *(const float4*)(A + (size_t)(row0 + row) * K + k0 + kq);
            uint4 u = make_uint4(f2tf32(v.x), f2tf32(v.y), f2tf32(v.z), f2tf32(v.w));
            *(uint4*)&As[buf][row * KPAD + kq] = u;
            float4 w = *(const float4*)(Bt + (size_t)(col0 + row) * K + k0 + kq);
            uint4 uw = make_uint4(f2tf32(w.x), f2tf32(w.y), f2tf32(w.z), f2tf32(w.w));
            *(uint4*)&Bs[buf][row * KPAD + kq] = uw;
        }
    };

    load_stage(0, 0);
    __syncthreads();

    for (int s = 0; s < S; s++) {
        int buf = s & 1;
        if (s + 1 < S) load_stage(s + 1, buf ^ 1);

        #pragma unroll
        for (int kk = 0; kk < 2; kk++) {
            uint32_t a[4][4], b[4][2];
            #pragma unroll
            for (int mt = 0; mt < 4; mt++) {
                int m = wm + mt * 16;
                int kb = kk * 8;
                a[mt][0] = As[buf][(m + gid)     * KPAD + kb + tig];
                a[mt][1] = As[buf][(m + gid + 8) * KPAD + kb + tig];
                a[mt][2] = As[buf][(m + gid)     * KPAD + kb + tig + 4];
                a[mt][3] = As[buf][(m + gid + 8) * KPAD + kb + tig + 4];
            }
            #pragma unroll
            for (int nt = 0; nt < 4; nt++) {
                int n = wn + nt * 8;
                int kb = kk * 8;
                b[nt][0] = Bs[buf][(n + gid) * KPAD + kb + tig];
                b[nt][1] = Bs[buf][(n + gid) * KPAD + kb + tig + 4];
            }
            #pragma unroll
            for (int mt = 0; mt < 4; mt++)
                #pragma unroll
                for (int nt = 0; nt < 4; nt++)
                    mma_tf32(acc[mt][nt], a[mt], b[nt]);
        }
        __syncthreads();
    }

    #pragma unroll
    for (int mt = 0; mt < 4; mt++) {
        int r0 = row0 + wm + mt * 16 + gid;
        int r1 = r0 + 8;
        #pragma unroll
        for (int nt = 0; nt < 4; nt++) {
            int c = col0 + wn + nt * 8 + tig * 2;
            float2 v0 = make_float2(acc[mt][nt][0], acc[mt][nt][1]);
            float2 v1 = make_float2(acc[mt][nt][2], acc[mt][nt][3]);
            if (EPI) {
                float bc0 = bias[c], bc1 = bias[c + 1];
                v0.x = fmaxf(v0.x + bc0, 0.f); v0.y = fmaxf(v0.y + bc1, 0.f);
                v1.x = fmaxf(v1.x + bc0, 0.f); v1.y = fmaxf(v1.y + bc1, 0.f);
            }
            if (r0 < M) *(float2*)(C + (size_t)r0 * N + c) = v0;
            if (r1 < M) *(float2*)(C + (size_t)r1 * N + c) = v1;
        }
    }
}

// ---------------- W[K][N] -> Wt[N][K] transpose ---------------------------------
__global__ __launch_bounds__(256)
void transpose_kernel(const float* __restrict__ W, float* __restrict__ Wt,
                      int K, int N)
{
    __shared__ float t[32][33];
    int n0 = blockIdx.x * 32, k0 = blockIdx.y * 32;
    int x = threadIdx.x, y0 = threadIdx.y;
    #pragma unroll
    for (int dy = 0; dy < 32; dy += 8) {
        int k = k0 + y0 + dy, n = n0 + x;
        t[y0 + dy][x] = (k < K && n < N) ? W[(size_t)k * N + n] : 0.f;
    }
    __syncthreads();
    #pragma unroll
    for (int dy = 0; dy < 32; dy += 8) {
        int n = n0 + y0 + dy, k = k0 + x;
        if (n < N && k < K) Wt[(size_t)n * K + k] = t[x][y0 + dy];
    }
}

// ---------------- edge-index dtype detection ------------------------------------
__global__ void detect_kernel(const void* __restrict__ ei)
{
    const long long* p = (const long long*)ei;
    int ok = 1;
    for (int i = 0; i < 64; i++) {
        long long v = p[i];
        if (v < 0 || v >= N_NODES) { ok = 0; break; }
    }
    g_ei64 = ok;
}

__device__ __forceinline__ bool edge_sd(const void* __restrict__ ei,
                                        int e, int& s, int& d)
{
    if (e >= N_EDGES) { s = d = e - N_EDGES; return true; }   // self loop
    if (g_ei64) {
        const long long* p = (const long long*)ei;
        s = (int)p[e];
        d = (int)p[N_EDGES + e];
    } else {
        const int* p = (const int*)ei;
        s = p[e];
        d = p[N_EDGES + e];
    }
    return ((unsigned)s < N_NODES) && ((unsigned)d < N_NODES);
}

// ======================  CSR build (once per launch)  ===========================
__global__ void zero_deg_kernel()
{
    int i = blockIdx.x * blockDim.x + threadIdx.x;
    if (i < N_NODES) g_deg[i] = 0;
}

__global__ void count_kernel(const void* __restrict__ ei)
{
    int e = blockIdx.x * blockDim.x + threadIdx.x;
    if (e >= E_TOT) return;
    int s, d;
    if (!edge_sd(ei, e, s, d)) return;
    atomicAdd(&g_deg[d], 1);
}

// single-block exclusive scan of g_deg -> g_rowptr (+ cursor copy)
__global__ __launch_bounds__(1024)
void scan_kernel()
{
    __shared__ int sa[1024], sb[1024];
    const int CH = (N_NODES + 1023) / 1024;       // 10
    int tid = threadIdx.x;
    int base = tid * CH;
    int local[CH];
    int s = 0;
    #pragma unroll
    for (int i = 0; i < CH; i++) {
        int idx = base + i;
        local[i] = s;
        s += (idx < N_NODES) ? g_deg[idx] : 0;
    }
    sa[tid] = s;
    __syncthreads();
    // inclusive Hillis-Steele scan, double-buffered
    int* src = sa; int* dst = sb;
    for (int off = 1; off < 1024; off <<= 1) {
        int v = src[tid];
        if (tid >= off) v += src[tid - off];
        dst[tid] = v;
        __syncthreads();
        int* tp = src; src = dst; dst = tp;
    }
    int excl = (tid > 0) ? src[tid - 1] : 0;
    #pragma unroll
    for (int i = 0; i < CH; i++) {
        int idx = base + i;
        if (idx < N_NODES) {
            int v = excl + local[i];
            g_rowptr[idx] = v;
            g_cursor[idx] = v;
        }
    }
    if (tid == 1023) g_rowptr[N_NODES] = src[1023];
}

__global__ void fill_kernel(const void* __restrict__ ei)
{
    int e = blockIdx.x * blockDim.x + threadIdx.x;
    if (e >= E_TOT) return;
    int s, d;
    if (!edge_sd(ei, e, s, d)) return;
    int pos = atomicAdd(&g_cursor[d], 1);
    g_col[pos] = s;
}

// ---------------- per-(node,head) attention logits: one warp each --------------
__global__ __launch_bounds__(256)
void alpha_kernel(const float* __restrict__ h, const float* __restrict__ a_src,
                  const float* __restrict__ a_dst,
                  float* __restrict__ as_o, float* __restrict__ ad_o)
{
    int warp = (blockIdx.x * blockDim.x + threadIdx.x) >> 5;
    int lane = threadIdx.x & 31;
    if (warp >= N_NODES * HEADS) return;
    int n  = warp / HEADS;
    int hd = warp % HEADS;
    const float* hp  = h + (size_t)n * F1 + hd * HID;
    const float* asp = a_src + hd * HID;
    const float* adp = a_dst + hd * HID;
    float s = 0.f, d = 0.f;
    #pragma unroll
    for (int i = lane; i < HID; i += 32) {
        float v = hp[i];
        s = fmaf(v, asp[i], s);
        d = fmaf(v, adp[i], d);
    }
    #pragma unroll
    for (int o = 16; o; o >>= 1) {
        s += __shfl_down_sync(0xffffffffu, s, o);
        d += __shfl_down_sync(0xffffffffu, d, o);
    }
    if (lane == 0) { as_o[warp] = s; ad_o[warp] = d; }
}

// ---------------- CSR softmax stats: one warp per node --------------------------
// lane = slot*8 + head; 4 slots stride the edge list; shfl-reduce over slots.
__global__ __launch_bounds__(256)
void csr_softmax_kernel(const float* __restrict__ as, const float* __restrict__ ad,
                        float* __restrict__ m, float* __restrict__ den)
{
    int warp = (blockIdx.x * blockDim.x + threadIdx.x) >> 5;
    int lane = threadIdx.x & 31;
    if (warp >= N_NODES) return;
    int d    = warp;
    int hd   = lane & 7;
    int slot = lane >> 3;
    int beg = g_rowptr[d], end = g_rowptr[d + 1];
    float adv = ad[d * HEADS + hd];

    float mx = -INFINITY;
    for (int i = beg + slot; i < end; i += 4) {
        float v = as[g_col[i] * HEADS + hd] + adv;
        v = v >= 0.f ? v : NEG_SLOPE * v;
        mx = fmaxf(mx, v);
    }
    mx = fmaxf(mx, __shfl_xor_sync(0xffffffffu, mx, 8));
    mx = fmaxf(mx, __shfl_xor_sync(0xffffffffu, mx, 16));

    float dn = 0.f;
    for (int i = beg + slot; i < end; i += 4) {
        float v = as[g_col[i] * HEADS + hd] + adv;
        v = v >= 0.f ? v : NEG_SLOPE * v;
        dn += expf(v - mx);
    }
    dn += __shfl_xor_sync(0xffffffffu, dn, 8);
    dn += __shfl_xor_sync(0xffffffffu, dn, 16);

    if (slot == 0) {
        m[d * HEADS + hd]   = mx;
        den[d * HEADS + hd] = dn;
    }
}

// ---------------- CSR gather: one CTA per dst node ------------------------------
// 256 threads x 8 channels each. EPI=1: +b1 then ELU -> out[N,2048].
// EPI=2: head-mean + b2 -> out[N,256] (smem reduction).
template<int EPI>
__global__ __launch_bounds__(256)
void gather_kernel(const float* __restrict__ h,
                   const float* __restrict__ as, const float* __restrict__ ad,
                   const float* __restrict__ m, const float* __restrict__ den,
                   const float* __restrict__ bias, float* __restrict__ out)
{
    __shared__ float red[F1];                 // used by EPI=2 only (8 KB)
    int d   = blockIdx.x;
    int tid = threadIdx.x;
    int ch  = tid * 8;
    int hd  = tid >> 5;                       // 256 channels per head
    int beg = g_rowptr[d], end = g_rowptr[d + 1];

    float md  = m[d * HEADS + hd];
    float dn  = den[d * HEADS + hd] + 1e-16f;
    float adv = ad[d * HEADS + hd];
    float inv = 1.f / dn;

    float acc[8];
    #pragma unroll
    for (int i = 0; i < 8; i++) acc[i] = 0.f;

    for (int i = beg; i < end; i++) {
        int s = g_col[i];
        float v = as[s * HEADS + hd] + adv;
        v = v >= 0.f ? v : NEG_SLOPE * v;
        float al = expf(v - md) * inv;
        const float4* hp = (const float4*)(h + (size_t)s * F1 + ch);
        float4 a0 = hp[0], a1 = hp[1];
        acc[0] = fmaf(al, a0.x, acc[0]); acc[1] = fmaf(al, a0.y, acc[1]);
        acc[2] = fmaf(al, a0.z, acc[2]); acc[3] = fmaf(al, a0.w, acc[3]);
        acc[4] = fmaf(al, a1.x, acc[4]); acc[5] = fmaf(al, a1.y, acc[5]);
        acc[6] = fmaf(al, a1.z, acc[6]); acc[7] = fmaf(al, a1.w, acc[7]);
    }

    if (EPI == 1) {
        float* op = out + (size_t)d * F1 + ch;
        #pragma unroll
        for (int j = 0; j < 8; j++) {
            float v = acc[j] + bias[ch + j];
            op[j] = v > 0.f ? v : (expf(v) - 1.f);
        }
    } else {
        #pragma unroll
        for (int j = 0; j < 8; j++) red[ch + j] = acc[j];
        __syncthreads();
        int c = tid;                           // 0..255
        float s = 0.f;
        #pragma unroll
        for (int hh = 0; hh < HEADS; hh++) s += red[hh * HID + c];
        out[(size_t)d * HID + c] = s * (1.f / HEADS) + bias[c];
    }
}

// ---------------- launch ---------------------------------------------------------
extern "C" void kernel_launch(void* const* d_in, const int* in_sizes, int n_in,
                              void* d_out, int out_size)
{
    const float* x      = (const float*)d_in[0];
    const void*  eindex = d_in[1];
    const float* W1     = (const float*)d_in[2];
    const float* a_src1 = (const float*)d_in[3];
    const float* a_dst1 = (const float*)d_in[4];
    const float* b1     = (const float*)d_in[5];
    const float* W2     = (const float*)d_in[6];
    const float* a_src2 = (const float*)d_in[7];
    const float* a_dst2 = (const float*)d_in[8];
    const float* b2     = (const float*)d_in[9];
    const float* Wp     = (const float*)d_in[10];
    const float* bp     = (const float*)d_in[11];
    float*       out    = (float*)d_out;

    float *h1, *agg1, *h2, *h2m, *as, *ad, *m, *den;
    float *wt1, *wt2, *wtp;
    cudaGetSymbolAddress((void**)&h1,   g_h1);
    cudaGetSymbolAddress((void**)&agg1, g_agg1);
    cudaGetSymbolAddress((void**)&h2,   g_h2);
    cudaGetSymbolAddress((void**)&h2m,  g_h2m);
    cudaGetSymbolAddress((void**)&as,   g_as);
    cudaGetSymbolAddress((void**)&ad,   g_ad);
    cudaGetSymbolAddress((void**)&m,    g_m);
    cudaGetSymbolAddress((void**)&den,  g_den);
    cudaGetSymbolAddress((void**)&wt1,  g_wt1);
    cudaGetSymbolAddress((void**)&wt2,  g_wt2);
    cudaGetSymbolAddress((void**)&wtp,  g_wtp);

    const int TB = 256;
    dim3 tblk(32, 8);
    const int MROWS = (N_NODES + 127) / 128;        // 79
    const int SWGRID = (N_NODES * 32 + TB - 1) / TB;

    detect_kernel<<<1, 1>>>(eindex);
    transpose_kernel<<<dim3(F1 / 32, IN_DIM / 32), tblk>>>(W1, wt1, IN_DIM, F1);
    transpose_kernel<<<dim3(F1 / 32, F1 / 32),     tblk>>>(W2, wt2, F1, F1);
    transpose_kernel<<<dim3(HID / 32, HID / 32),   tblk>>>(Wp, wtp, HID, HID);

    // ---- CSR build (graph is launch-invariant) ----
    zero_deg_kernel<<<(N_NODES + TB - 1) / TB, TB>>>();
    count_kernel<<<(E_TOT + TB - 1) / TB, TB>>>(eindex);
    scan_kernel<<<1, 1024>>>();
    fill_kernel<<<(E_TOT + TB - 1) / TB, TB>>>(eindex);

    // ---- layer 1 ----
    mma_gemm_kernel<0><<<dim3(F1 / 128, MROWS), 256>>>(x, wt1, h1,
                                                       N_NODES, F1, IN_DIM, nullptr);
    alpha_kernel<<<(N_NODES * HEADS * 32 + TB - 1) / TB, TB>>>(h1, a_src1, a_dst1, as, ad);
    csr_softmax_kernel<<<SWGRID, TB>>>(as, ad, m, den);
    gather_kernel<1><<<N_NODES, TB>>>(h1, as, ad, m, den, b1, agg1);

    // ---- layer 2 ----
    mma_gemm_kernel<0><<<dim3(F1 / 128, MROWS), 256>>>(agg1, wt2, h2,
                                                       N_NODES, F1, F1, nullptr);
    alpha_kernel<<<(N_NODES * HEADS * 32 + TB - 1) / TB, TB>>>(h2, a_src2, a_dst2, as, ad);
    csr_softmax_kernel<<<SWGRID, TB>>>(as, ad, m, den);
    gather_kernel<2><<<N_NODES, TB>>>(h2, as, ad, m, den, b2, h2m);

    // ---- projection + relu ----
    mma_gemm_kernel<1><<<dim3(HID / 128, MROWS), 256>>>(h2m, wtp, out,
                                                        N_NODES, HID, HID, bp);
}

// round 10
// speedup vs baseline: 3.3410x; 1.0697x over previous
#include <cuda_runtime.h>
#include <math.h>
#include <stdint.h>

#define N_NODES 10000
#define N_EDGES 80000
#define E_TOT   90000      // edges + self loops
#define IN_DIM  768
#define HID     256
#define HEADS   8
#define F1      (HEADS*HID)   // 2048
#define NEG_SLOPE 0.2f

// ---------------- scratch (static device globals; no allocation) ----------------
__device__ float g_h1  [(size_t)N_NODES * F1];   // x @ W1
__device__ float g_agg1[(size_t)N_NODES * F1];   // layer-1 aggregated + bias + ELU
__device__ float g_h2  [(size_t)N_NODES * F1];   // agg1 @ W2
__device__ float g_h2m [(size_t)N_NODES * HID];  // layer-2 aggregated head-mean + b2
__device__ float g_as  [N_NODES * HEADS];
__device__ float g_ad  [N_NODES * HEADS];
__device__ float g_m   [N_NODES * HEADS];
__device__ float g_den [N_NODES * HEADS];
__device__ int   g_ei64;                         // 1 if edge_index stored as int64
// CSR by dst
__device__ int   g_deg   [N_NODES];
__device__ int   g_rowptr[N_NODES + 1];
__device__ int   g_cursor[N_NODES];
__device__ int   g_col   [E_TOT];                // src node per CSR slot

// ======================  tf32 mma.sync GEMM  ====================================
// C[M,N] = A[M,K] @ W[K,N].  CTA tile 128x128, 8 warps (2x4), warp tile 64x32,
// m16n8k8 tf32 frags, BK=16 double-buffered. W read K-major directly (no
// pre-transpose): Bs stored [k][n] with NPAD=136 -> conflict-free frag loads.
__device__ __forceinline__ uint32_t f2tf32(float f) {
    uint32_t u;
    asm("cvt.rna.tf32.f32 %0, %1;" : "=r"(u) : "f"(f));
    return u;
}

__device__ __forceinline__ void mma_tf32(float* c, const uint32_t* a, const uint32_t* b) {
    asm volatile(
        "mma.sync.aligned.m16n8k8.row.col.f32.tf32.tf32.f32 "
        "{%0,%1,%2,%3}, {%4,%5,%6,%7}, {%8,%9}, {%0,%1,%2,%3};"
        : "+f"(c[0]), "+f"(c[1]), "+f"(c[2]), "+f"(c[3])
        : "r"(a[0]), "r"(a[1]), "r"(a[2]), "r"(a[3]), "r"(b[0]), "r"(b[1]));
}

#define BKK  16
#define KPAD 20    // A: 16 + 4 pad -> conflict-free A-fragment loads
#define NPAD 136   // B: 128 + 8 pad -> bank = tig*8+gid, all distinct

template<int EPI>   // 0 = plain store, 1 = +bias then relu
__global__ __launch_bounds__(256, 2)
void mma_gemm_kernel(const float* __restrict__ A, const float* __restrict__ W,
                     float* __restrict__ C, int M, int N, int K,
                     const float* __restrict__ bias)
{
    __shared__ __align__(16) uint32_t As[2][128 * KPAD];
    __shared__ __align__(16) uint32_t Bs[2][BKK * NPAD];

    const int tid  = threadIdx.x;
    const int lane = tid & 31;
    const int wid  = tid >> 5;
    const int gid  = lane >> 2;
    const int tig  = lane & 3;
    const int wm   = (wid & 1) * 64;
    const int wn   = (wid >> 1) * 32;
    const int row0 = blockIdx.y * 128;
    const int col0 = blockIdx.x * 128;

    float acc[4][4][4];
    #pragma unroll
    for (int mt = 0; mt < 4; mt++)
        #pragma unroll
        for (int nt = 0; nt < 4; nt++)
            #pragma unroll
            for (int i = 0; i < 4; i++) acc[mt][nt][i] = 0.f;

    const int S = K / BKK;

    auto load_stage = [&](int s, int buf) {
        int k0 = s * BKK;
        // A: 128 rows x 16 k = 512 float4
        #pragma unroll
        for (int t = 0; t < 2; t++) {
            int idx = tid + t * 256;
            int row = idx >> 2;
            int kq  = (idx & 3) * 4;
            float4 v = make_float4(0.f, 0.f, 0.f, 0.f);
            if (row0 + row < M)
                v = *(const float4*)(A + (size_t)(row0 + row) * K + k0 + kq);
            uint4 u = make_uint4(f2tf32(v.x), f2tf32(v.y), f2tf32(v.z), f2tf32(v.w));
            *(uint4*)&As[buf][row * KPAD + kq] = u;
        }
        // B: 16 k x 128 n = 512 float4, read K-major from W (coalesced along n)
        #pragma unroll
        for (int t = 0; t < 2; t++) {
            int idx = tid + t * 256;
            int kk = idx >> 5;              // 0..15
            int nq = (idx & 31) * 4;        // 0..124
            float4 w = *(const float4*)(W + (size_t)(k0 + kk) * N + col0 + nq);
            uint4 uw = make_uint4(f2tf32(w.x), f2tf32(w.y), f2tf32(w.z), f2tf32(w.w));
            *(uint4*)&Bs[buf][kk * NPAD + nq] = uw;
        }
    };

    load_stage(0, 0);
    __syncthreads();

    for (int s = 0; s < S; s++) {
        int buf = s & 1;
        if (s + 1 < S) load_stage(s + 1, buf ^ 1);

        #pragma unroll
        for (int kk = 0; kk < 2; kk++) {
            uint32_t a[4][4], b[4][2];
            int kb = kk * 8;
            #pragma unroll
            for (int mt = 0; mt < 4; mt++) {
                int m = wm + mt * 16;
                a[mt][0] = As[buf][(m + gid)     * KPAD + kb + tig];
                a[mt][1] = As[buf][(m + gid + 8) * KPAD + kb + tig];
                a[mt][2] = As[buf][(m + gid)     * KPAD + kb + tig + 4];
                a[mt][3] = As[buf][(m + gid + 8) * KPAD + kb + tig + 4];
            }
            #pragma unroll
            for (int nt = 0; nt < 4; nt++) {
                int n = wn + nt * 8 + gid;
                b[nt][0] = Bs[buf][(kb + tig)     * NPAD + n];
                b[nt][1] = Bs[buf][(kb + tig + 4) * NPAD + n];
            }
            #pragma unroll
            for (int mt = 0; mt < 4; mt++)
                #pragma unroll
                for (int nt = 0; nt < 4; nt++)
                    mma_tf32(acc[mt][nt], a[mt], b[nt]);
        }
        __syncthreads();
    }

    #pragma unroll
    for (int mt = 0; mt < 4; mt++) {
        int r0 = row0 + wm + mt * 16 + gid;
        int r1 = r0 + 8;
        #pragma unroll
        for (int nt = 0; nt < 4; nt++) {
            int c = col0 + wn + nt * 8 + tig * 2;
            float2 v0 = make_float2(acc[mt][nt][0], acc[mt][nt][1]);
            float2 v1 = make_float2(acc[mt][nt][2], acc[mt][nt][3]);
            if (EPI) {
                float bc0 = bias[c], bc1 = bias[c + 1];
                v0.x = fmaxf(v0.x + bc0, 0.f); v0.y = fmaxf(v0.y + bc1, 0.f);
                v1.x = fmaxf(v1.x + bc0, 0.f); v1.y = fmaxf(v1.y + bc1, 0.f);
            }
            if (r0 < M) *(float2*)(C + (size_t)r0 * N + c) = v0;
            if (r1 < M) *(float2*)(C + (size_t)r1 * N + c) = v1;
        }
    }
}

// ---------------- edge-index dtype detection ------------------------------------
__global__ void detect_kernel(const void* __restrict__ ei)
{
    const long long* p = (const long long*)ei;
    int ok = 1;
    for (int i = 0; i < 64; i++) {
        long long v = p[i];
        if (v < 0 || v >= N_NODES) { ok = 0; break; }
    }
    g_ei64 = ok;
}

__device__ __forceinline__ bool edge_sd(const void* __restrict__ ei,
                                        int e, int& s, int& d)
{
    if (e >= N_EDGES) { s = d = e - N_EDGES; return true; }   // self loop
    if (g_ei64) {
        const long long* p = (const long long*)ei;
        s = (int)p[e];
        d = (int)p[N_EDGES + e];
    } else {
        const int* p = (const int*)ei;
        s = p[e];
        d = p[N_EDGES + e];
    }
    return ((unsigned)s < N_NODES) && ((unsigned)d < N_NODES);
}

// ======================  CSR build (once per launch)  ===========================
__global__ void zero_deg_kernel()
{
    int i = blockIdx.x * blockDim.x + threadIdx.x;
    if (i < N_NODES) g_deg[i] = 0;
}

__global__ void count_kernel(const void* __restrict__ ei)
{
    int e = blockIdx.x * blockDim.x + threadIdx.x;
    if (e >= E_TOT) return;
    int s, d;
    if (!edge_sd(ei, e, s, d)) return;
    atomicAdd(&g_deg[d], 1);
}

// single-block exclusive scan of g_deg -> g_rowptr (+ cursor copy)
__global__ __launch_bounds__(1024)
void scan_kernel()
{
    __shared__ int sa[1024], sb[1024];
    const int CH = (N_NODES + 1023) / 1024;       // 10
    int tid = threadIdx.x;
    int base = tid * CH;
    int local[CH];
    int s = 0;
    #pragma unroll
    for (int i = 0; i < CH; i++) {
        int idx = base + i;
        local[i] = s;
        s += (idx < N_NODES) ? g_deg[idx] : 0;
    }
    sa[tid] = s;
    __syncthreads();
    int* src = sa; int* dst = sb;
    for (int off = 1; off < 1024; off <<= 1) {
        int v = src[tid];
        if (tid >= off) v += src[tid - off];
        dst[tid] = v;
        __syncthreads();
        int* tp = src; src = dst; dst = tp;
    }
    int excl = (tid > 0) ? src[tid - 1] : 0;
    #pragma unroll
    for (int i = 0; i < CH; i++) {
        int idx = base + i;
        if (idx < N_NODES) {
            int v = excl + local[i];
            g_rowptr[idx] = v;
            g_cursor[idx] = v;
        }
    }
    if (tid == 1023) g_rowptr[N_NODES] = src[1023];
}

__global__ void fill_kernel(const void* __restrict__ ei)
{
    int e = blockIdx.x * blockDim.x + threadIdx.x;
    if (e >= E_TOT) return;
    int s, d;
    if (!edge_sd(ei, e, s, d)) return;
    int pos = atomicAdd(&g_cursor[d], 1);
    g_col[pos] = s;
}

// ---------------- per-(node,head) attention logits: one warp each --------------
__global__ __launch_bounds__(256)
void alpha_kernel(const float* __restrict__ h, const float* __restrict__ a_src,
                  const float* __restrict__ a_dst,
                  float* __restrict__ as_o, float* __restrict__ ad_o)
{
    int warp = (blockIdx.x * blockDim.x + threadIdx.x) >> 5;
    int lane = threadIdx.x & 31;
    if (warp >= N_NODES * HEADS) return;
    int n  = warp / HEADS;
    int hd = warp % HEADS;
    const float* hp  = h + (size_t)n * F1 + hd * HID;
    const float* asp = a_src + hd * HID;
    const float* adp = a_dst + hd * HID;
    float s = 0.f, d = 0.f;
    #pragma unroll
    for (int i = lane; i < HID; i += 32) {
        float v = hp[i];
        s = fmaf(v, asp[i], s);
        d = fmaf(v, adp[i], d);
    }
    #pragma unroll
    for (int o = 16; o; o >>= 1) {
        s += __shfl_down_sync(0xffffffffu, s, o);
        d += __shfl_down_sync(0xffffffffu, d, o);
    }
    if (lane == 0) { as_o[warp] = s; ad_o[warp] = d; }
}

// ---------------- CSR softmax stats: one warp per node --------------------------
__global__ __launch_bounds__(256)
void csr_softmax_kernel(const float* __restrict__ as, const float* __restrict__ ad,
                        float* __restrict__ m, float* __restrict__ den)
{
    int warp = (blockIdx.x * blockDim.x + threadIdx.x) >> 5;
    int lane = threadIdx.x & 31;
    if (warp >= N_NODES) return;
    int d    = warp;
    int hd   = lane & 7;
    int slot = lane >> 3;
    int beg = g_rowptr[d], end = g_rowptr[d + 1];
    float adv = ad[d * HEADS + hd];

    float mx = -INFINITY;
    for (int i = beg + slot; i < end; i += 4) {
        float v = as[g_col[i] * HEADS + hd] + adv;
        v = v >= 0.f ? v : NEG_SLOPE * v;
        mx = fmaxf(mx, v);
    }
    mx = fmaxf(mx, __shfl_xor_sync(0xffffffffu, mx, 8));
    mx = fmaxf(mx, __shfl_xor_sync(0xffffffffu, mx, 16));

    float dn = 0.f;
    for (int i = beg + slot; i < end; i += 4) {
        float v = as[g_col[i] * HEADS + hd] + adv;
        v = v >= 0.f ? v : NEG_SLOPE * v;
        dn += expf(v - mx);
    }
    dn += __shfl_xor_sync(0xffffffffu, dn, 8);
    dn += __shfl_xor_sync(0xffffffffu, dn, 16);

    if (slot == 0) {
        m[d * HEADS + hd]   = mx;
        den[d * HEADS + hd] = dn;
    }
}

// ---------------- CSR gather: one CTA per dst node ------------------------------
// 256 threads x 8 channels each. EPI=1: +b1 then ELU -> out[N,2048].
// EPI=2: head-mean + b2 -> out[N,256] (smem reduction).
template<int EPI>
__global__ __launch_bounds__(256)
void gather_kernel(const float* __restrict__ h,
                   const float* __restrict__ as, const float* __restrict__ ad,
                   const float* __restrict__ m, const float* __restrict__ den,
                   const float* __restrict__ bias, float* __restrict__ out)
{
    __shared__ float red[F1];                 // used by EPI=2 only (8 KB)
    int d   = blockIdx.x;
    int tid = threadIdx.x;
    int ch  = tid * 8;
    int hd  = tid >> 5;                       // 256 channels per head
    int beg = g_rowptr[d], end = g_rowptr[d + 1];

    float md  = m[d * HEADS + hd];
    float dn  = den[d * HEADS + hd] + 1e-16f;
    float adv = ad[d * HEADS + hd];
    float inv = 1.f / dn;

    float acc[8];
    #pragma unroll
    for (int i = 0; i < 8; i++) acc[i] = 0.f;

    for (int i = beg; i < end; i++) {
        int s = g_col[i];
        float v = as[s * HEADS + hd] + adv;
        v = v >= 0.f ? v : NEG_SLOPE * v;
        float al = expf(v - md) * inv;
        const float4* hp = (const float4*)(h + (size_t)s * F1 + ch);
        float4 a0 = hp[0], a1 = hp[1];
        acc[0] = fmaf(al, a0.x, acc[0]); acc[1] = fmaf(al, a0.y, acc[1]);
        acc[2] = fmaf(al, a0.z, acc[2]); acc[3] = fmaf(al, a0.w, acc[3]);
        acc[4] = fmaf(al, a1.x, acc[4]); acc[5] = fmaf(al, a1.y, acc[5]);
        acc[6] = fmaf(al, a1.z, acc[6]); acc[7] = fmaf(al, a1.w, acc[7]);
    }

    if (EPI == 1) {
        float* op = out + (size_t)d * F1 + ch;
        #pragma unroll
        for (int j = 0; j < 8; j++) {
            float v = acc[j] + bias[ch + j];
            op[j] = v > 0.f ? v : (expf(v) - 1.f);
        }
    } else {
        #pragma unroll
        for (int j = 0; j < 8; j++) red[ch + j] = acc[j];
        __syncthreads();
        int c = tid;                           // 0..255
        float s = 0.f;
        #pragma unroll
        for (int hh = 0; hh < HEADS; hh++) s += red[hh * HID + c];
        out[(size_t)d * HID + c] = s * (1.f / HEADS) + bias[c];
    }
}

// ---------------- launch ---------------------------------------------------------
extern "C" void kernel_launch(void* const* d_in, const int* in_sizes, int n_in,
                              void* d_out, int out_size)
{
    const float* x      = (const float*)d_in[0];
    const void*  eindex = d_in[1];
    const float* W1     = (const float*)d_in[2];
    const float* a_src1 = (const float*)d_in[3];
    const float* a_dst1 = (const float*)d_in[4];
    const float* b1     = (const float*)d_in[5];
    const float* W2     = (const float*)d_in[6];
    const float* a_src2 = (const float*)d_in[7];
    const float* a_dst2 = (const float*)d_in[8];
    const float* b2     = (const float*)d_in[9];
    const float* Wp     = (const float*)d_in[10];
    const float* bp     = (const float*)d_in[11];
    float*       out    = (float*)d_out;

    float *h1, *agg1, *h2, *h2m, *as, *ad, *m, *den;
    cudaGetSymbolAddress((void**)&h1,   g_h1);
    cudaGetSymbolAddress((void**)&agg1, g_agg1);
    cudaGetSymbolAddress((void**)&h2,   g_h2);
    cudaGetSymbolAddress((void**)&h2m,  g_h2m);
    cudaGetSymbolAddress((void**)&as,   g_as);
    cudaGetSymbolAddress((void**)&ad,   g_ad);
    cudaGetSymbolAddress((void**)&m,    g_m);
    cudaGetSymbolAddress((void**)&den,  g_den);

    const int TB = 256;
    const int MROWS = (N_NODES + 127) / 128;        // 79
    const int SWGRID = (N_NODES * 32 + TB - 1) / TB;

    detect_kernel<<<1, 1>>>(eindex);

    // ---- CSR build (graph is launch-invariant) ----
    zero_deg_kernel<<<(N_NODES + TB - 1) / TB, TB>>>();
    count_kernel<<<(E_TOT + TB - 1) / TB, TB>>>(eindex);
    scan_kernel<<<1, 1024>>>();
    fill_kernel<<<(E_TOT + TB - 1) / TB, TB>>>(eindex);

    // ---- layer 1 ----
    mma_gemm_kernel<0><<<dim3(F1 / 128, MROWS), 256>>>(x, W1, h1,
                                                       N_NODES, F1, IN_DIM, nullptr);
    alpha_kernel<<<(N_NODES * HEADS * 32 + TB - 1) / TB, TB>>>(h1, a_src1, a_dst1, as, ad);
    csr_softmax_kernel<<<SWGRID, TB>>>(as, ad, m, den);
    gather_kernel<1><<<N_NODES, TB>>>(h1, as, ad, m, den, b1, agg1);

    // ---- layer 2 ----
    mma_gemm_kernel<0><<<dim3(F1 / 128, MROWS), 256>>>(agg1, W2, h2,
                                                       N_NODES, F1, F1, nullptr);
    alpha_kernel<<<(N_NODES * HEADS * 32 + TB - 1) / TB, TB>>>(h2, a_src2, a_dst2, as, ad);
    csr_softmax_kernel<<<SWGRID, TB>>>(as, ad, m, den);
    gather_kernel<2><<<N_NODES, TB>>>(h2, as, ad, m, den, b2, h2m);

    // ---- projection + relu ----
    mma_gemm_kernel<1><<<dim3(HID / 128, MROWS), 256>>>(h2m, Wp, out,
                                                        N_NODES, HID, HID, bp);
}